// round 8
// baseline (speedup 1.0000x reference)
#include <cuda_runtime.h>

// LightGCN propagation, gather formulation, fp32 end-to-end:
//   e0 = concat(user_emb, item_emb)           (N = 300000, D = 64)
//   e_{l+1}[r] = sum_{edges e: rows[e]==r} vals[e] * e_l[cols[e]]
//   out = (e0 + e1 + e2 + e3) / 4
//
// Instruction-minimized gather: 16 lanes per row (2 rows/warp), uniform-load
// edge entries (no shuffles), packed fma.rn.f32x2 accumulation (2 instr/edge
// instead of 4 FFMA), fp32 sources (no half<->float cvts). Profile showed the
// gather is issue-bound (60.5% issue, 11% DRAM), so instrs/edge is the lever.

#define DIM      64
#define DIM4     16              // float4 per row
#define PAD_W    32              // padded CSR width (deg ~ Poisson(13.3))
#define NMAX     300000
#define OVF_CAP  4096
#define TPB      256

// ---- static scratch (alloc-free rule) -------------------------------------
__device__ int   g_cnt[NMAX];                      // per-row degree/cursor
__device__ uint2 g_list[(size_t)NMAX * PAD_W];     // {col, val_bits}  76.8MB
__device__ int   g_ovf_cnt;
__device__ int4  g_ovf[OVF_CAP];                   // {row, col, val_bits, 0}
__device__ float g_e0[(size_t)NMAX * DIM];         // e0 (fp32, unified)
__device__ float g_e1[(size_t)NMAX * DIM];         // e1
__device__ float g_e2[(size_t)NMAX * DIM];         // e2

// ---- packed f32x2 helpers --------------------------------------------------
__device__ __forceinline__ void fma2(unsigned long long& acc,
                                     unsigned long long x,
                                     unsigned long long v2) {
    asm("fma.rn.f32x2 %0, %1, %2, %0;" : "+l"(acc) : "l"(x), "l"(v2));
}
__device__ __forceinline__ unsigned long long pack_dup(unsigned vbits) {
    unsigned long long v2;
    asm("mov.b64 %0, {%1, %1};" : "=l"(v2) : "r"(vbits));
    return v2;
}
__device__ __forceinline__ float2 unpack_f2(unsigned long long a) {
    float2 r;
    asm("mov.b64 {%0, %1}, %2;" : "=f"(r.x), "=f"(r.y) : "l"(a));
    return r;
}

// ---- prep: zero counters + copy concat(user,item) -> g_e0 ------------------
__global__ void lg_prep(const float4* __restrict__ user,
                        const float4* __restrict__ item,
                        int n_user4, int n4, int n_rows) {
    int i = blockIdx.x * blockDim.x + threadIdx.x;
    if (i < n_rows) g_cnt[i] = 0;
    if (i == 0) g_ovf_cnt = 0;
    if (i >= n4) return;
    reinterpret_cast<float4*>(g_e0)[i] =
        (i < n_user4) ? user[i] : item[i - n_user4];
}

// ---- build padded CSR, 4 edges per thread ----------------------------------
__global__ void lg_build4(const int4* __restrict__ rows4,
                          const int4* __restrict__ cols4,
                          const float4* __restrict__ vals4,
                          const int* __restrict__ rows,
                          const int* __restrict__ cols,
                          const float* __restrict__ vals,
                          int nq, int nnz) {
    int i = blockIdx.x * blockDim.x + threadIdx.x;
    if (i < nq) {
        int4   r = rows4[i];
        int4   c = cols4[i];
        float4 v = vals4[i];
        int rr[4] = {r.x, r.y, r.z, r.w};
        int cc[4] = {c.x, c.y, c.z, c.w};
        float vv[4] = {v.x, v.y, v.z, v.w};
        #pragma unroll
        for (int k = 0; k < 4; k++) {
            int pos = atomicAdd(&g_cnt[rr[k]], 1);
            if (pos < PAD_W) {
                g_list[(size_t)rr[k] * PAD_W + pos] =
                    make_uint2((unsigned)cc[k], __float_as_uint(vv[k]));
            } else {
                int o = atomicAdd(&g_ovf_cnt, 1);
                if (o < OVF_CAP)
                    g_ovf[o] = make_int4(rr[k], cc[k], __float_as_int(vv[k]), 0);
            }
        }
    }
    // scalar tail (<= 3 edges)
    if (i == 0) {
        for (int e = nq * 4; e < nnz; e++) {
            int pos = atomicAdd(&g_cnt[rows[e]], 1);
            if (pos < PAD_W) {
                g_list[(size_t)rows[e] * PAD_W + pos] =
                    make_uint2((unsigned)cols[e], __float_as_uint(vals[e]));
            } else {
                int o = atomicAdd(&g_ovf_cnt, 1);
                if (o < OVF_CAP)
                    g_ovf[o] = make_int4(rows[e], cols[e],
                                         __float_as_int(vals[e]), 0);
            }
        }
    }
}

// ---- per-row gather core: 16 lanes/row, f32x2 accumulation -----------------
// acc = {xy, zw} packed pairs for this lane's float4 slice of the row.
__device__ __forceinline__ void row_gather(const ulonglong2* __restrict__ src,
                                           int row, int sub,
                                           unsigned long long& aA,
                                           unsigned long long& aB) {
    int deg = g_cnt[row];
    if (deg > PAD_W) deg = PAD_W;
    const uint2* lst = g_list + (size_t)row * PAD_W;

    #pragma unroll 4
    for (int j = 0; j < deg; j++) {
        uint2 ent = lst[j];                       // uniform in half-warp
        unsigned long long v2 = pack_dup(ent.y);
        ulonglong2 x = src[(size_t)ent.x * DIM4 + sub];
        fma2(aA, x.x, v2);
        fma2(aB, x.y, v2);
    }

    int novf = g_ovf_cnt;                         // ~always 0
    if (novf > 0) {
        if (novf > OVF_CAP) novf = OVF_CAP;
        for (int k = 0; k < novf; k++) {
            int4 rec = g_ovf[k];
            if (rec.x == row) {
                unsigned long long v2 = pack_dup((unsigned)rec.z);
                ulonglong2 x = src[(size_t)rec.y * DIM4 + sub];
                fma2(aA, x.x, v2);
                fma2(aB, x.y, v2);
            }
        }
    }
}

// ---- gather SpMM (middle layers) -------------------------------------------
__global__ void lg_gather(const ulonglong2* __restrict__ src,
                          ulonglong2* __restrict__ dst, int n_rows) {
    int tid = blockIdx.x * blockDim.x + threadIdx.x;
    int row = tid >> 4;                 // 16 lanes per row
    int sub = tid & 15;
    if (row >= n_rows) return;
    unsigned long long aA = 0ull, aB = 0ull;
    row_gather(src, row, sub, aA, aB);
    ulonglong2 o; o.x = aA; o.y = aB;
    dst[(size_t)row * DIM4 + sub] = o;
}

// ---- layer-3 gather fused with the final mean ------------------------------
__global__ void lg_gather_final(const ulonglong2* __restrict__ src,   // e2
                                const float4* __restrict__ e0,
                                const float4* __restrict__ e1,
                                const float4* __restrict__ e2,
                                float4* __restrict__ out, int n_rows) {
    int tid = blockIdx.x * blockDim.x + threadIdx.x;
    int row = tid >> 4;
    int sub = tid & 15;
    if (row >= n_rows) return;
    unsigned long long aA = 0ull, aB = 0ull;
    row_gather(src, row, sub, aA, aB);            // e3 (packed fp32)

    size_t idx = (size_t)row * DIM4 + sub;
    float4 v0 = e0[idx];
    float4 v1 = e1[idx];
    float4 v2 = e2[idx];
    float2 e3a = unpack_f2(aA);
    float2 e3b = unpack_f2(aB);

    float4 r;
    r.x = (v0.x + v1.x + v2.x + e3a.x) * 0.25f;
    r.y = (v0.y + v1.y + v2.y + e3a.y) * 0.25f;
    r.z = (v0.z + v1.z + v2.z + e3b.x) * 0.25f;
    r.w = (v0.w + v1.w + v2.w + e3b.y) * 0.25f;
    out[idx] = r;
}

extern "C" void kernel_launch(void* const* d_in, const int* in_sizes, int n_in,
                              void* d_out, int out_size) {
    const float* user = (const float*)d_in[0];
    const float* item = (const float*)d_in[1];
    const float* vals = (const float*)d_in[2];
    const int*   rows = (const int*)d_in[3];
    const int*   cols = (const int*)d_in[4];

    int n_user  = in_sizes[0] / DIM;
    int n_item  = in_sizes[1] / DIM;
    int nnz     = in_sizes[2];
    int n_total = n_user + n_item;
    int n4      = n_total * DIM4;

    float* out = (float*)d_out;

    float* e0; float* e1; float* e2;
    cudaGetSymbolAddress((void**)&e0, g_e0);
    cudaGetSymbolAddress((void**)&e1, g_e1);
    cudaGetSymbolAddress((void**)&e2, g_e2);

    int prep_blocks   = (n4 + TPB - 1) / TPB;
    int nq            = nnz >> 2;
    int build_blocks  = (nq + TPB - 1) / TPB;
    int gather_blocks = (n_total * 16 + TPB - 1) / TPB;   // 16 lanes/row

    lg_prep<<<prep_blocks, TPB>>>((const float4*)user, (const float4*)item,
                                  n_user * DIM4, n4, n_total);
    lg_build4<<<build_blocks, TPB>>>((const int4*)rows, (const int4*)cols,
                                     (const float4*)vals, rows, cols, vals,
                                     nq, nnz);

    lg_gather<<<gather_blocks, TPB>>>((const ulonglong2*)e0,
                                      (ulonglong2*)e1, n_total);      // e1
    lg_gather<<<gather_blocks, TPB>>>((const ulonglong2*)e1,
                                      (ulonglong2*)e2, n_total);      // e2
    lg_gather_final<<<gather_blocks, TPB>>>((const ulonglong2*)e2,
                                            (const float4*)e0,
                                            (const float4*)e1,
                                            (const float4*)e2,
                                            (float4*)out, n_total);   // e3+mean
}

// round 11
// speedup vs baseline: 1.3577x; 1.3577x over previous
#include <cuda_runtime.h>
#include <cuda_fp16.h>

// LightGCN propagation — gather formulation combining the two proven wins:
//   * fp16 embedding storage  -> 38.4MB table stays L2-resident, one 128B
//     L1 line per edge gather                         (R6 win: bytes/latency)
//   * 16 lanes per row, uniform edge-entry loads, no shuffles -> 2 edges per
//     warp instruction, ~6 warp-instrs/edge           (R8 win: issue count)
// fp32 accumulation in registers; fp16 layer outputs; fp32 final mean.
//
//   e0 = concat(user_emb, item_emb)   (N = 300000, D = 64)
//   e_{l+1}[r] = sum_{e: rows[e]==r} vals[e] * e_l[cols[e]]
//   out = (e0 + e1 + e2 + e3) / 4

#define DIM      64
#define DIM4     16              // 4-element groups per row
#define PAD_W    32              // padded CSR width (deg ~ Poisson(13.3))
#define NMAX     300000
#define OVF_CAP  4096
#define TPB      256

// ---- static scratch (alloc-free rule) -------------------------------------
__device__ int   g_cnt[NMAX];                      // per-row degree/cursor
__device__ uint2 g_list[(size_t)NMAX * PAD_W];     // {col, val_bits}  76.8MB
__device__ int   g_ovf_cnt;
__device__ int4  g_ovf[OVF_CAP];                   // {row, col, val_bits, 0}
__device__ float g_e0[(size_t)NMAX * DIM];         // e0 fp32 (for final mean)
__device__ uint2 g_h0[(size_t)NMAX * DIM4];        // e0 fp16 (gather source)
__device__ uint2 g_h1[(size_t)NMAX * DIM4];        // e1 fp16
__device__ uint2 g_h2[(size_t)NMAX * DIM4];        // e2 fp16

// ---- helpers ---------------------------------------------------------------
__device__ __forceinline__ uint2 f4_to_h4(float4 v) {
    __half2 a = __floats2half2_rn(v.x, v.y);
    __half2 b = __floats2half2_rn(v.z, v.w);
    uint2 r;
    r.x = *reinterpret_cast<unsigned*>(&a);
    r.y = *reinterpret_cast<unsigned*>(&b);
    return r;
}
__device__ __forceinline__ float2 h2_to_f2(unsigned h) {
    return __half22float2(*reinterpret_cast<__half2*>(&h));
}

// ---- prep: zero counters + e0 -> fp32 copy + fp16 copy ---------------------
__global__ void lg_prep(const float4* __restrict__ user,
                        const float4* __restrict__ item,
                        int n_user4, int n4, int n_rows) {
    int i = blockIdx.x * blockDim.x + threadIdx.x;
    if (i < n_rows) g_cnt[i] = 0;
    if (i == 0) g_ovf_cnt = 0;
    if (i >= n4) return;
    float4 v = (i < n_user4) ? user[i] : item[i - n_user4];
    reinterpret_cast<float4*>(g_e0)[i] = v;
    g_h0[i] = f4_to_h4(v);
}

// ---- build padded CSR, 4 edges per thread ----------------------------------
__global__ void lg_build4(const int4* __restrict__ rows4,
                          const int4* __restrict__ cols4,
                          const float4* __restrict__ vals4,
                          const int* __restrict__ rows,
                          const int* __restrict__ cols,
                          const float* __restrict__ vals,
                          int nq, int nnz) {
    int i = blockIdx.x * blockDim.x + threadIdx.x;
    if (i < nq) {
        int4   r = rows4[i];
        int4   c = cols4[i];
        float4 v = vals4[i];
        int rr[4] = {r.x, r.y, r.z, r.w};
        int cc[4] = {c.x, c.y, c.z, c.w};
        float vv[4] = {v.x, v.y, v.z, v.w};
        #pragma unroll
        for (int k = 0; k < 4; k++) {
            int pos = atomicAdd(&g_cnt[rr[k]], 1);
            if (pos < PAD_W) {
                g_list[(size_t)rr[k] * PAD_W + pos] =
                    make_uint2((unsigned)cc[k], __float_as_uint(vv[k]));
            } else {
                int o = atomicAdd(&g_ovf_cnt, 1);
                if (o < OVF_CAP)
                    g_ovf[o] = make_int4(rr[k], cc[k], __float_as_int(vv[k]), 0);
            }
        }
    }
    if (i == 0) {                                   // scalar tail (<= 3 edges)
        for (int e = nq * 4; e < nnz; e++) {
            int pos = atomicAdd(&g_cnt[rows[e]], 1);
            if (pos < PAD_W) {
                g_list[(size_t)rows[e] * PAD_W + pos] =
                    make_uint2((unsigned)cols[e], __float_as_uint(vals[e]));
            } else {
                int o = atomicAdd(&g_ovf_cnt, 1);
                if (o < OVF_CAP)
                    g_ovf[o] = make_int4(rows[e], cols[e],
                                         __float_as_int(vals[e]), 0);
            }
        }
    }
}

// ---- per-row gather core: 16 lanes/row, fp16 src, fp32 accumulate ----------
__device__ __forceinline__ float4 row_gather(const uint2* __restrict__ src,
                                             int row, unsigned sub) {
    int deg = g_cnt[row];
    if (deg > PAD_W) deg = PAD_W;
    const uint2* lst = g_list + (size_t)row * PAD_W;

    float4 acc = make_float4(0.f, 0.f, 0.f, 0.f);

    #pragma unroll 4
    for (int j = 0; j < deg; j++) {
        uint2 ent = lst[j];                        // uniform per half-warp
        float v = __uint_as_float(ent.y);
        uint2 xh = src[ent.x * 16u + sub];         // 8B: this lane's 4 halfs
        float2 a = h2_to_f2(xh.x);
        float2 b = h2_to_f2(xh.y);
        acc.x += v * a.x;
        acc.y += v * a.y;
        acc.z += v * b.x;
        acc.w += v * b.y;
    }

    int novf = g_ovf_cnt;                          // ~always 0
    if (novf > 0) {
        if (novf > OVF_CAP) novf = OVF_CAP;
        for (int k = 0; k < novf; k++) {
            int4 rec = g_ovf[k];
            if (rec.x == row) {
                float v = __int_as_float(rec.z);
                uint2 xh = src[(unsigned)rec.y * 16u + sub];
                float2 a = h2_to_f2(xh.x);
                float2 b = h2_to_f2(xh.y);
                acc.x += v * a.x;
                acc.y += v * a.y;
                acc.z += v * b.x;
                acc.w += v * b.y;
            }
        }
    }
    return acc;
}

// ---- gather SpMM into a fp16 buffer ----------------------------------------
__global__ void lg_gather(const uint2* __restrict__ src,
                          uint2* __restrict__ dst, int n_rows) {
    int tid = blockIdx.x * blockDim.x + threadIdx.x;
    int row = tid >> 4;                  // 16 lanes per row
    unsigned sub = tid & 15;
    if (row >= n_rows) return;
    float4 acc = row_gather(src, row, sub);
    dst[(size_t)row * DIM4 + sub] = f4_to_h4(acc);
}

// ---- layer-3 gather fused with the final mean ------------------------------
__global__ void lg_gather_final(const uint2* __restrict__ src,    // e2 fp16
                                const float4* __restrict__ e0,
                                const uint2* __restrict__ h1,
                                const uint2* __restrict__ h2,
                                float4* __restrict__ out, int n_rows) {
    int tid = blockIdx.x * blockDim.x + threadIdx.x;
    int row = tid >> 4;
    unsigned sub = tid & 15;
    if (row >= n_rows) return;
    float4 acc = row_gather(src, row, sub);        // e3 in fp32 regs

    size_t idx = (size_t)row * DIM4 + sub;
    float4 v0 = e0[idx];
    uint2 x1 = h1[idx];
    uint2 x2 = h2[idx];
    float2 a1 = h2_to_f2(x1.x), b1 = h2_to_f2(x1.y);
    float2 a2 = h2_to_f2(x2.x), b2 = h2_to_f2(x2.y);

    float4 r;
    r.x = (v0.x + a1.x + a2.x + acc.x) * 0.25f;
    r.y = (v0.y + a1.y + a2.y + acc.y) * 0.25f;
    r.z = (v0.z + b1.x + b2.x + acc.z) * 0.25f;
    r.w = (v0.w + b1.y + b2.y + acc.w) * 0.25f;
    out[idx] = r;
}

extern "C" void kernel_launch(void* const* d_in, const int* in_sizes, int n_in,
                              void* d_out, int out_size) {
    const float* user = (const float*)d_in[0];
    const float* item = (const float*)d_in[1];
    const float* vals = (const float*)d_in[2];
    const int*   rows = (const int*)d_in[3];
    const int*   cols = (const int*)d_in[4];

    int n_user  = in_sizes[0] / DIM;
    int n_item  = in_sizes[1] / DIM;
    int nnz     = in_sizes[2];
    int n_total = n_user + n_item;
    int n4      = n_total * DIM4;

    float* out = (float*)d_out;

    float* e0; uint2* h0; uint2* h1; uint2* h2;
    cudaGetSymbolAddress((void**)&e0, g_e0);
    cudaGetSymbolAddress((void**)&h0, g_h0);
    cudaGetSymbolAddress((void**)&h1, g_h1);
    cudaGetSymbolAddress((void**)&h2, g_h2);

    int prep_blocks   = (n4 + TPB - 1) / TPB;
    int nq            = nnz >> 2;
    int build_blocks  = (nq + TPB - 1) / TPB;
    int gather_blocks = (n_total * 16 + TPB - 1) / TPB;   // 16 lanes/row

    lg_prep<<<prep_blocks, TPB>>>((const float4*)user, (const float4*)item,
                                  n_user * DIM4, n4, n_total);
    lg_build4<<<build_blocks, TPB>>>((const int4*)rows, (const int4*)cols,
                                     (const float4*)vals, rows, cols, vals,
                                     nq, nnz);

    lg_gather<<<gather_blocks, TPB>>>(h0, h1, n_total);            // e1
    lg_gather<<<gather_blocks, TPB>>>(h1, h2, n_total);            // e2
    lg_gather_final<<<gather_blocks, TPB>>>(h2, (const float4*)e0,
                                            h1, h2,
                                            (float4*)out, n_total); // e3+mean
}